// round 7
// baseline (speedup 1.0000x reference)
#include <cuda_runtime.h>
#include <cstdint>

#define NN 10000
#define NE 160000

// ---------------- device scratch (no allocations allowed) ----------------
// RULE (round-6 lesson): these are NEVER passed as kernel arguments from host
// code. On GB300, host code taking a __device__ symbol's address yields the
// host shadow (.bss), which ATS makes silently GPU-accessible -> reads zeros.
// All kernels reference these directly in device code.
__device__ int   g_is32;                         // 1 if edge_index is int32
__device__ int   g_swap1;                        // 1 if first 128-buf is b1
__device__ int   g_cnt[NN];
__device__ int   g_rowptr[NN + 1];
__device__ int   g_cursor[NN];
__device__ int   g_es[NE];                       // src sorted by dst
__device__ float g_ews[NE];                      // weights sorted by dst
__device__ float g_s[NN];                        // A @ x
__device__ float g_h1[NN * 128];                 // layer1 output
__device__ float g_agg2[NN * 128];               // A @ h1
__device__ float g_h2[NN * 256];                 // layer2 output
__device__ float g_agg3[NN * 256];               // A @ h2

// ---------------- input disambiguation ----------------
__global__ void detect_kernel(const long long* __restrict__ ei, int force) {
    if (threadIdx.x == 0) {
        if (force >= 0) { g_is32 = force; return; }
        int is32 = 0;
        for (int i = 0; i < 64; i++) {
            long long v = ei[i];
            if (v < 0 || v >= NN) { is32 = 1; break; }
        }
        g_is32 = is32;
    }
}

__global__ void pick_w1_kernel(const float* __restrict__ u) {
    __shared__ int any;
    if (threadIdx.x == 0) any = 0;
    __syncthreads();
    if (u[threadIdx.x] != 0.0f) atomicExch(&any, 1);
    __syncthreads();
    if (threadIdx.x == 0) g_swap1 = (any == 0) ? 1 : 0;
}

__device__ __forceinline__ int load_idx(const void* ei, int pos) {
    if (g_is32) return ((const int*)ei)[pos];
    return (int)((const long long*)ei)[pos];
}

// ---------------- CSR build (reference semantics) ----------------
// msg = h[src] * w ; agg[dst] += msg   with src = edge_index[0] (pos e),
//                                          dst = edge_index[1] (pos NE+e)
__global__ void zero_cnt_kernel() {
    int i = blockIdx.x * blockDim.x + threadIdx.x;
    if (i < NN) g_cnt[i] = 0;
}

__global__ void hist_kernel(const void* __restrict__ ei) {
    int e = blockIdx.x * blockDim.x + threadIdx.x;
    if (e >= NE) return;
    int d = load_idx(ei, NE + e);
    if (d >= 0 && d < NN) atomicAdd(&g_cnt[d], 1);
}

__global__ void scan_kernel() {
    __shared__ int part[1024];
    const int IPT = 10;  // 1024 * 10 >= NN
    int t = threadIdx.x;
    int base = t * IPT;
    int v[IPT];
    int run = 0;
#pragma unroll
    for (int i = 0; i < IPT; i++) {
        int idx = base + i;
        int c = (idx < NN) ? g_cnt[idx] : 0;
        v[i] = run;
        run += c;
    }
    part[t] = run;
    __syncthreads();
    for (int off = 1; off < 1024; off <<= 1) {
        int val = (t >= off) ? part[t - off] : 0;
        __syncthreads();
        part[t] += val;
        __syncthreads();
    }
    int excl = part[t] - run;
#pragma unroll
    for (int i = 0; i < IPT; i++) {
        int idx = base + i;
        if (idx < NN) {
            int rp = excl + v[i];
            g_rowptr[idx] = rp;
            g_cursor[idx] = rp;
        }
    }
    if (t == 1023) g_rowptr[NN] = part[1023];
}

__global__ void scatter_kernel(const void* __restrict__ ei,
                               const float* __restrict__ ew) {
    int e = blockIdx.x * blockDim.x + threadIdx.x;
    if (e >= NE) return;
    int s = load_idx(ei, e);
    int d = load_idx(ei, NE + e);
    if (d < 0 || d >= NN || s < 0 || s >= NN) return;
    int pos = atomicAdd(&g_cursor[d], 1);
    g_es[pos] = s;
    g_ews[pos] = ew[e];
}

// ---------------- layer 1: s = A x ; h1 = s (outer) W1 + b1 ----------------
__global__ void spmm1_kernel(const float* __restrict__ x) {
    int i = blockIdx.x * blockDim.x + threadIdx.x;
    if (i >= NN) return;
    int p = g_rowptr[i], end = g_rowptr[i + 1];
    float sum = 0.f;
    for (; p < end; p++) sum += g_ews[p] * x[g_es[p]];
    g_s[i] = sum;
}

__global__ void expand1_kernel(const float* __restrict__ u,
                               const float* __restrict__ v) {
    int tid = blockIdx.x * blockDim.x + threadIdx.x;
    if (tid >= NN * 128) return;
    int i = tid >> 7, j = tid & 127;
    float w = g_swap1 ? v[j] : u[j];
    float b = g_swap1 ? u[j] : v[j];
    g_h1[tid] = g_s[i] * w + b;
}

// ---------------- SpMM layer 2: g_agg2 = A @ g_h1 (F=128) -----------------
__global__ void spmm2_kernel() {
    int idx = blockIdx.x * blockDim.x + threadIdx.x;
    if (idx >= NN * 128) return;
    int node = idx >> 7;
    int f = idx & 127;
    int p = g_rowptr[node], end = g_rowptr[node + 1];
    float acc = 0.f;
    for (; p < end; p++) acc += g_ews[p] * g_h1[g_es[p] * 128 + f];
    g_agg2[idx] = acc;
}

// ---------------- GEMM layer 2: g_h2 = g_agg2 @ W2 + b2 (K=128,N=256) -----
__global__ void gemm2_kernel(const float* __restrict__ B,
                             const float* __restrict__ bias) {
    int idx = blockIdx.x * blockDim.x + threadIdx.x;
    if (idx >= NN * 256) return;
    int r = idx >> 8;
    int c = idx & 255;
    const float* arow = g_agg2 + r * 128;
    float acc = 0.f;
#pragma unroll 8
    for (int k = 0; k < 128; k++) acc += arow[k] * B[k * 256 + c];
    g_h2[idx] = acc + bias[c];
}

// ---------------- SpMM layer 3: g_agg3 = A @ g_h2 (F=256) -----------------
__global__ void spmm3_kernel() {
    int idx = blockIdx.x * blockDim.x + threadIdx.x;
    if (idx >= NN * 256) return;
    int node = idx >> 8;
    int f = idx & 255;
    int p = g_rowptr[node], end = g_rowptr[node + 1];
    float acc = 0.f;
    for (; p < end; p++) acc += g_ews[p] * g_h2[g_es[p] * 256 + f];
    g_agg3[idx] = acc;
}

// ---------------- GEMM layer 3: out = sigmoid(g_agg3 @ W3 + b3) -----------
__global__ void gemm3_kernel(const float* __restrict__ B,
                             const float* __restrict__ bias,
                             float* __restrict__ C) {
    int idx = blockIdx.x * blockDim.x + threadIdx.x;
    if (idx >= NN * 512) return;
    int r = idx >> 9;
    int c = idx & 511;
    const float* arow = g_agg3 + r * 256;
    float acc = 0.f;
#pragma unroll 8
    for (int k = 0; k < 256; k++) acc += arow[k] * B[k * 512 + c];
    acc += bias[c];
    C[idx] = 1.f / (1.f + __expf(-acc));
}

// ---------------- launch ----------------
extern "C" void kernel_launch(void* const* d_in, const int* in_sizes, int n_in,
                              void* d_out, int out_size) {
    const float* x = 0;  const void* ei = 0;  const float* ew = 0;
    const float* u128 = 0; const float* v128 = 0;   // W1/b1 pair (ambiguous)
    const float* W2 = 0; const float* b2 = 0;
    const float* W3 = 0; const float* b3 = 0;
    int ei_words = 0;
    for (int i = 0; i < n_in; i++) {
        int sz = in_sizes[i];
        const void* p = d_in[i];
        switch (sz) {
            case 10000:  x  = (const float*)p; break;
            case 320000: ei = p; ei_words = sz; break;
            case 640000: ei = p; ei_words = sz; break;
            case 160000: ew = (const float*)p; break;
            case 128:    if (!u128) u128 = (const float*)p; else v128 = (const float*)p; break;
            case 32768:  W2 = (const float*)p; break;
            case 256:    b2 = (const float*)p; break;
            case 131072: W3 = (const float*)p; break;
            case 512:    b3 = (const float*)p; break;
            default: break;
        }
    }
    if (!x || !ei || !ew || !u128 || !v128 || !W2 || !b2 || !W3 || !b3) {
        x  = (const float*)d_in[0]; ei = d_in[1]; ew = (const float*)d_in[2];
        u128 = (const float*)d_in[3]; v128 = (const float*)d_in[4];
        W2 = (const float*)d_in[5]; b2 = (const float*)d_in[6];
        W3 = (const float*)d_in[7]; b3 = (const float*)d_in[8];
        ei_words = in_sizes[1];
    }
    int force = (ei_words == 4 * NE) ? 0 : -1;
    float* out = (float*)d_out;

    // disambiguation + CSR build
    detect_kernel<<<1, 32>>>((const long long*)ei, force);
    pick_w1_kernel<<<1, 128>>>(u128);
    zero_cnt_kernel<<<(NN + 255) / 256, 256>>>();
    hist_kernel<<<(NE + 255) / 256, 256>>>(ei);
    scan_kernel<<<1, 1024>>>();
    scatter_kernel<<<(NE + 255) / 256, 256>>>(ei, ew);

    // layer 1: s = A x ; h1 = s * W1 + b1
    spmm1_kernel<<<(NN + 255) / 256, 256>>>(x);
    expand1_kernel<<<(NN * 128 + 255) / 256, 256>>>(u128, v128);

    // layer 2: agg2 = A h1 ; h2 = agg2 @ W2 + b2
    spmm2_kernel<<<(NN * 128 + 255) / 256, 256>>>();
    gemm2_kernel<<<(NN * 256 + 255) / 256, 256>>>(W2, b2);

    // layer 3: agg3 = A h2 ; out = sigmoid(agg3 @ W3 + b3)
    spmm3_kernel<<<(NN * 256 + 255) / 256, 256>>>();
    gemm3_kernel<<<(NN * 512 + 255) / 256, 256>>>(W3, b3, out);
}

// round 9
// speedup vs baseline: 2.4247x; 2.4247x over previous
#include <cuda_runtime.h>
#include <cstdint>

#define NN 10000
#define NE 160000

// ---------------- device scratch (no allocations allowed) ----------------
// RULE (round-6 lesson): never passed as kernel arguments from host code
// (GB300 ATS would resolve the host .bss shadow). Device code references only.
__device__ int   g_is32;
__device__ int   g_swap1;
__device__ int   g_cnt[NN];
__device__ int   g_rowptr[NN + 1];
__device__ int   g_cursor[NN];
__device__ int   g_es[NE];
__device__ __align__(16) float g_ews[NE];
__device__ __align__(16) float g_s[NN];
__device__ __align__(16) float g_h1[NN * 128];
__device__ __align__(16) float g_agg2[NN * 128];
__device__ __align__(16) float g_h2[NN * 256];
__device__ __align__(16) float g_agg3[NN * 256];

// ---------------- input disambiguation ----------------
__global__ void detect_kernel(const long long* __restrict__ ei, int force) {
    if (threadIdx.x == 0) {
        if (force >= 0) { g_is32 = force; return; }
        int is32 = 0;
        for (int i = 0; i < 64; i++) {
            long long v = ei[i];
            if (v < 0 || v >= NN) { is32 = 1; break; }
        }
        g_is32 = is32;
    }
}

__global__ void pick_w1_kernel(const float* __restrict__ u) {
    __shared__ int any;
    if (threadIdx.x == 0) any = 0;
    __syncthreads();
    if (u[threadIdx.x] != 0.0f) atomicExch(&any, 1);
    __syncthreads();
    if (threadIdx.x == 0) g_swap1 = (any == 0) ? 1 : 0;
}

__device__ __forceinline__ int load_idx(const void* ei, int pos) {
    if (g_is32) return ((const int*)ei)[pos];
    return (int)((const long long*)ei)[pos];
}

// ---------------- CSR build (src = edge_index[0], dst = edge_index[1]) -----
__global__ void zero_cnt_kernel() {
    int i = blockIdx.x * blockDim.x + threadIdx.x;
    if (i < NN) g_cnt[i] = 0;
}

__global__ void hist_kernel(const void* __restrict__ ei) {
    int e = blockIdx.x * blockDim.x + threadIdx.x;
    if (e >= NE) return;
    int d = load_idx(ei, NE + e);
    if (d >= 0 && d < NN) atomicAdd(&g_cnt[d], 1);
}

__global__ void scan_kernel() {
    __shared__ int part[1024];
    const int IPT = 10;
    int t = threadIdx.x;
    int base = t * IPT;
    int v[IPT];
    int run = 0;
#pragma unroll
    for (int i = 0; i < IPT; i++) {
        int idx = base + i;
        int c = (idx < NN) ? g_cnt[idx] : 0;
        v[i] = run;
        run += c;
    }
    part[t] = run;
    __syncthreads();
    for (int off = 1; off < 1024; off <<= 1) {
        int val = (t >= off) ? part[t - off] : 0;
        __syncthreads();
        part[t] += val;
        __syncthreads();
    }
    int excl = part[t] - run;
#pragma unroll
    for (int i = 0; i < IPT; i++) {
        int idx = base + i;
        if (idx < NN) {
            int rp = excl + v[i];
            g_rowptr[idx] = rp;
            g_cursor[idx] = rp;
        }
    }
    if (t == 1023) g_rowptr[NN] = part[1023];
}

__global__ void scatter_kernel(const void* __restrict__ ei,
                               const float* __restrict__ ew) {
    int e = blockIdx.x * blockDim.x + threadIdx.x;
    if (e >= NE) return;
    int s = load_idx(ei, e);
    int d = load_idx(ei, NE + e);
    if (d < 0 || d >= NN || s < 0 || s >= NN) return;
    int pos = atomicAdd(&g_cursor[d], 1);
    g_es[pos] = s;
    g_ews[pos] = ew[e];
}

// ---------------- layer 1: s = A x ; h1 = s (outer) W1 + b1 ----------------
__global__ void spmm1_kernel(const float* __restrict__ x) {
    int i = blockIdx.x * blockDim.x + threadIdx.x;
    if (i >= NN) return;
    int p = g_rowptr[i], end = g_rowptr[i + 1];
    float sum = 0.f;
    for (; p < end; p++) sum += g_ews[p] * x[g_es[p]];
    g_s[i] = sum;
}

__global__ void expand1_kernel(const float* __restrict__ u,
                               const float* __restrict__ v) {
    int tid = blockIdx.x * blockDim.x + threadIdx.x;
    if (tid >= NN * 128) return;
    int i = tid >> 7, j = tid & 127;
    float w = g_swap1 ? v[j] : u[j];
    float b = g_swap1 ? u[j] : v[j];
    g_h1[tid] = g_s[i] * w + b;
}

// ---------------- SpMM: warp per (node, 128-float chunk), float4 ----------
template <int LAYER>  // 2: g_agg2 = A g_h1 (F=128); 3: g_agg3 = A g_h2 (F=256)
__global__ void spmm_kernel() {
    constexpr int F = (LAYER == 2) ? 128 : 256;
    constexpr int CH = F / 128;
    const float* H = (LAYER == 2) ? g_h1 : g_h2;
    float* OUT = (LAYER == 2) ? g_agg2 : g_agg3;

    int wid = (blockIdx.x * blockDim.x + threadIdx.x) >> 5;
    int lane = threadIdx.x & 31;
    if (wid >= NN * CH) return;
    int node = wid / CH;
    int ch = wid - node * CH;
    int col = ch * 128 + lane * 4;
    int p = g_rowptr[node], end = g_rowptr[node + 1];
    float4 acc = make_float4(0.f, 0.f, 0.f, 0.f);
    for (; p < end; p++) {
        int s = g_es[p];
        float w = g_ews[p];
        float4 v = *(const float4*)(H + s * F + col);
        acc.x += w * v.x;
        acc.y += w * v.y;
        acc.z += w * v.z;
        acc.w += w * v.w;
    }
    *(float4*)(OUT + node * F + col) = acc;
}

// ---------------- tiled SGEMM + bias (+sigmoid on layer 3) ----------------
// LAYER 2: g_h2 = g_agg2 @ W2 + b2          (M=NN, N=256, K=128)
// LAYER 3: out  = sigmoid(g_agg3 @ W3 + b3) (M=NN, N=512, K=256)
template <int LAYER>
__global__ void sgemm_kernel(const float* __restrict__ B,
                             const float* __restrict__ bias,
                             float* __restrict__ Cext) {
    constexpr int N = (LAYER == 2) ? 256 : 512;
    constexpr int K = (LAYER == 2) ? 128 : 256;
    constexpr int M = NN;
    const float* A = (LAYER == 2) ? g_agg2 : g_agg3;
    float* C = (LAYER == 2) ? g_h2 : Cext;

    __shared__ float As[8][128];
    __shared__ float Bs[8][128];
    int tid = threadIdx.x;
    int bm = blockIdx.y * 128;
    int bn = blockIdx.x * 128;

    int arow = tid >> 1;            // 0..127
    int acol4 = (tid & 1) * 4;      // 0 or 4
    int brow = tid >> 5;            // 0..7
    int bcol = (tid & 31) * 4;      // 0..124

    int tx = (tid & 15) * 8;        // col in tile
    int ty = (tid >> 4) * 8;        // row in tile

    float acc[8][8];
#pragma unroll
    for (int i = 0; i < 8; i++)
#pragma unroll
        for (int j = 0; j < 8; j++) acc[i][j] = 0.f;

    for (int k0 = 0; k0 < K; k0 += 8) {
        int gr = bm + arow;
        float4 av = make_float4(0.f, 0.f, 0.f, 0.f);
        if (gr < M) av = *(const float4*)(A + gr * K + k0 + acol4);
        As[acol4 + 0][arow] = av.x;
        As[acol4 + 1][arow] = av.y;
        As[acol4 + 2][arow] = av.z;
        As[acol4 + 3][arow] = av.w;
        float4 bv = *(const float4*)(B + (k0 + brow) * N + bn + bcol);
        *(float4*)&Bs[brow][bcol] = bv;
        __syncthreads();
#pragma unroll
        for (int k = 0; k < 8; k++) {
            float ra[8], rb[8];
            *(float4*)&ra[0] = *(const float4*)&As[k][ty];
            *(float4*)&ra[4] = *(const float4*)&As[k][ty + 4];
            *(float4*)&rb[0] = *(const float4*)&Bs[k][tx];
            *(float4*)&rb[4] = *(const float4*)&Bs[k][tx + 4];
#pragma unroll
            for (int i = 0; i < 8; i++)
#pragma unroll
                for (int j = 0; j < 8; j++) acc[i][j] += ra[i] * rb[j];
        }
        __syncthreads();
    }

#pragma unroll
    for (int i = 0; i < 8; i++) {
        int r = bm + ty + i;
        if (r >= M) continue;
#pragma unroll
        for (int j = 0; j < 8; j += 4) {
            int c = bn + tx + j;
            float4 bv = *(const float4*)(bias + c);
            float4 v;
            v.x = acc[i][j + 0] + bv.x;
            v.y = acc[i][j + 1] + bv.y;
            v.z = acc[i][j + 2] + bv.z;
            v.w = acc[i][j + 3] + bv.w;
            if (LAYER == 3) {
                v.x = 1.f / (1.f + __expf(-v.x));
                v.y = 1.f / (1.f + __expf(-v.y));
                v.z = 1.f / (1.f + __expf(-v.z));
                v.w = 1.f / (1.f + __expf(-v.w));
            }
            *(float4*)(C + r * N + c) = v;
        }
    }
}

// ---------------- launch ----------------
extern "C" void kernel_launch(void* const* d_in, const int* in_sizes, int n_in,
                              void* d_out, int out_size) {
    const float* x = 0;  const void* ei = 0;  const float* ew = 0;
    const float* u128 = 0; const float* v128 = 0;
    const float* W2 = 0; const float* b2 = 0;
    const float* W3 = 0; const float* b3 = 0;
    int ei_words = 0;
    for (int i = 0; i < n_in; i++) {
        int sz = in_sizes[i];
        const void* p = d_in[i];
        switch (sz) {
            case 10000:  x  = (const float*)p; break;
            case 320000: ei = p; ei_words = sz; break;
            case 640000: ei = p; ei_words = sz; break;
            case 160000: ew = (const float*)p; break;
            case 128:    if (!u128) u128 = (const float*)p; else v128 = (const float*)p; break;
            case 32768:  W2 = (const float*)p; break;
            case 256:    b2 = (const float*)p; break;
            case 131072: W3 = (const float*)p; break;
            case 512:    b3 = (const float*)p; break;
            default: break;
        }
    }
    if (!x || !ei || !ew || !u128 || !v128 || !W2 || !b2 || !W3 || !b3) {
        x  = (const float*)d_in[0]; ei = d_in[1]; ew = (const float*)d_in[2];
        u128 = (const float*)d_in[3]; v128 = (const float*)d_in[4];
        W2 = (const float*)d_in[5]; b2 = (const float*)d_in[6];
        W3 = (const float*)d_in[7]; b3 = (const float*)d_in[8];
        ei_words = in_sizes[1];
    }
    int force = (ei_words == 4 * NE) ? 0 : -1;
    float* out = (float*)d_out;

    // disambiguation + CSR build
    detect_kernel<<<1, 32>>>((const long long*)ei, force);
    pick_w1_kernel<<<1, 128>>>(u128);
    zero_cnt_kernel<<<(NN + 255) / 256, 256>>>();
    hist_kernel<<<(NE + 255) / 256, 256>>>(ei);
    scan_kernel<<<1, 1024>>>();
    scatter_kernel<<<(NE + 255) / 256, 256>>>(ei, ew);

    // layer 1
    spmm1_kernel<<<(NN + 255) / 256, 256>>>(x);
    expand1_kernel<<<(NN * 128 + 255) / 256, 256>>>(u128, v128);

    // layer 2
    spmm_kernel<2><<<(NN * 1 * 32 + 255) / 256, 256>>>();
    {
        dim3 grid(256 / 128, (NN + 127) / 128);
        sgemm_kernel<2><<<grid, 256>>>(W2, b2, nullptr);
    }

    // layer 3
    spmm_kernel<3><<<(NN * 2 * 32 + 255) / 256, 256>>>();
    {
        dim3 grid(512 / 128, (NN + 127) / 128);
        sgemm_kernel<3><<<grid, 256>>>(W3, b3, out);
    }
}

// round 10
// speedup vs baseline: 6.2756x; 2.5882x over previous
#include <cuda_runtime.h>
#include <cstdint>

#define NN 10000
#define NE 160000

// ---------------- device scratch (no allocations allowed) ----------------
// RULE (round-6 lesson): never passed as kernel arguments from host code
// (GB300 ATS resolves the host .bss shadow silently). Device-code refs only.
__device__ int   g_is32;
__device__ int   g_cnt[NN];
__device__ int   g_rowptr[NN + 1];
__device__ int   g_cursor[NN];
__device__ int   g_es[NE];
__device__ float g_ews[NE];
// rank-collapsed per-node scalars
__device__ float g_sx[NN];    // s  = A x
__device__ float g_deg[NN];   // deg = A 1
__device__ float g_t[NN];     // t  = A s
__device__ float g_d2[NN];    // d2 = A deg
__device__ float g_t2[NN];    // t2 = A t
// small factor vectors
__device__ __align__(16) float g_u[256];   // u = w1 @ W2
__device__ __align__(16) float g_v[256];   // v = b1 @ W2
__device__ __align__(16) float g_p[512];   // p = u @ W3
__device__ __align__(16) float g_q[512];   // q = v @ W3
__device__ __align__(16) float g_r[512];   // r = b2 @ W3

// ---------------- edge-index dtype detection ----------------
__global__ void detect_kernel(const long long* __restrict__ ei, int force) {
    if (threadIdx.x == 0) {
        if (force >= 0) { g_is32 = force; return; }
        int is32 = 0;
        for (int i = 0; i < 64; i++) {
            long long v = ei[i];
            if (v < 0 || v >= NN) { is32 = 1; break; }
        }
        g_is32 = is32;
    }
}

__device__ __forceinline__ int load_idx(const void* ei, int pos) {
    if (g_is32) return ((const int*)ei)[pos];
    return (int)((const long long*)ei)[pos];
}

// ---------------- CSR build (src = edge_index[0], dst = edge_index[1]) -----
__global__ void zero_cnt_kernel() {
    int i = blockIdx.x * blockDim.x + threadIdx.x;
    if (i < NN) g_cnt[i] = 0;
}

__global__ void hist_kernel(const void* __restrict__ ei) {
    int e = blockIdx.x * blockDim.x + threadIdx.x;
    if (e >= NE) return;
    int d = load_idx(ei, NE + e);
    if (d >= 0 && d < NN) atomicAdd(&g_cnt[d], 1);
}

__global__ void scan_kernel() {
    __shared__ int part[1024];
    const int IPT = 10;
    int t = threadIdx.x;
    int base = t * IPT;
    int v[IPT];
    int run = 0;
#pragma unroll
    for (int i = 0; i < IPT; i++) {
        int idx = base + i;
        int c = (idx < NN) ? g_cnt[idx] : 0;
        v[i] = run;
        run += c;
    }
    part[t] = run;
    __syncthreads();
    for (int off = 1; off < 1024; off <<= 1) {
        int val = (t >= off) ? part[t - off] : 0;
        __syncthreads();
        part[t] += val;
        __syncthreads();
    }
    int excl = part[t] - run;
#pragma unroll
    for (int i = 0; i < IPT; i++) {
        int idx = base + i;
        if (idx < NN) {
            int rp = excl + v[i];
            g_rowptr[idx] = rp;
            g_cursor[idx] = rp;
        }
    }
    if (t == 1023) g_rowptr[NN] = part[1023];
}

__global__ void scatter_kernel(const void* __restrict__ ei,
                               const float* __restrict__ ew) {
    int e = blockIdx.x * blockDim.x + threadIdx.x;
    if (e >= NE) return;
    int s = load_idx(ei, e);
    int d = load_idx(ei, NE + e);
    if (d < 0 || d >= NN || s < 0 || s >= NN) return;
    int pos = atomicAdd(&g_cursor[d], 1);
    g_es[pos] = s;
    g_ews[pos] = ew[e];
}

// ---------------- SpMV passes (thread per node, ~16 edges/row) ------------
// pass1: s = A x ; deg = A 1
__global__ void spmv_pass1_kernel(const float* __restrict__ x) {
    int i = blockIdx.x * blockDim.x + threadIdx.x;
    if (i >= NN) return;
    int p = g_rowptr[i], end = g_rowptr[i + 1];
    float s = 0.f, dg = 0.f;
    for (; p < end; p++) {
        float w = g_ews[p];
        s += w * x[g_es[p]];
        dg += w;
    }
    g_sx[i] = s;
    g_deg[i] = dg;
}

// pass2: t = A s ; d2 = A deg
__global__ void spmv_pass2_kernel() {
    int i = blockIdx.x * blockDim.x + threadIdx.x;
    if (i >= NN) return;
    int p = g_rowptr[i], end = g_rowptr[i + 1];
    float t = 0.f, d2 = 0.f;
    for (; p < end; p++) {
        float w = g_ews[p];
        int s = g_es[p];
        t  += w * g_sx[s];
        d2 += w * g_deg[s];
    }
    g_t[i] = t;
    g_d2[i] = d2;
}

// pass3: t2 = A t
__global__ void spmv_pass3_kernel() {
    int i = blockIdx.x * blockDim.x + threadIdx.x;
    if (i >= NN) return;
    int p = g_rowptr[i], end = g_rowptr[i + 1];
    float t2 = 0.f;
    for (; p < end; p++) t2 += g_ews[p] * g_t[g_es[p]];
    g_t2[i] = t2;
}

// ---------------- GEMV 2: u = w1 @ W2, v = b1 @ W2 (one block, 256 thr) ---
// Folds W1/b1 disambiguation: bias is exactly zero, Glorot weights are not.
__global__ void gemv2_kernel(const float* __restrict__ u128,
                             const float* __restrict__ v128,
                             const float* __restrict__ W2) {
    __shared__ int any;
    if (threadIdx.x == 0) any = 0;
    __syncthreads();
    if (threadIdx.x < 128 && u128[threadIdx.x] != 0.0f) atomicExch(&any, 1);
    __syncthreads();
    const float* w1 = (any == 0) ? v128 : u128;
    const float* b1 = (any == 0) ? u128 : v128;

    int c = threadIdx.x;  // 0..255
    float u = 0.f, v = 0.f;
#pragma unroll 8
    for (int j = 0; j < 128; j++) {
        float wv = W2[j * 256 + c];
        u += w1[j] * wv;
        v += b1[j] * wv;
    }
    g_u[c] = u;
    g_v[c] = v;
}

// ---------------- GEMV 3: p = u@W3, q = v@W3, r = b2@W3 (one block, 512) --
__global__ void gemv3_kernel(const float* __restrict__ W3,
                             const float* __restrict__ b2) {
    int c = threadIdx.x;  // 0..511
    float p = 0.f, q = 0.f, r = 0.f;
#pragma unroll 8
    for (int k = 0; k < 256; k++) {
        float wv = W3[k * 512 + c];
        p += g_u[k] * wv;
        q += g_v[k] * wv;
        r += b2[k] * wv;
    }
    g_p[c] = p;
    g_q[c] = q;
    g_r[c] = r;
}

// ---------------- final: out[i,c] = sigmoid(t2*p + d2*q + deg*r + b3) -----
__global__ void final_kernel(const float* __restrict__ b3,
                             float* __restrict__ out) {
    int idx = blockIdx.x * blockDim.x + threadIdx.x;  // NN*128 threads
    if (idx >= NN * 128) return;
    int i = idx >> 7;
    int c4 = (idx & 127) * 4;
    float t2 = g_t2[i], d2 = g_d2[i], dg = g_deg[i];
    float4 p = *(const float4*)(g_p + c4);
    float4 q = *(const float4*)(g_q + c4);
    float4 r = *(const float4*)(g_r + c4);
    float4 b = *(const float4*)(b3 + c4);
    float4 o;
    o.x = 1.f / (1.f + __expf(-(t2 * p.x + d2 * q.x + dg * r.x + b.x)));
    o.y = 1.f / (1.f + __expf(-(t2 * p.y + d2 * q.y + dg * r.y + b.y)));
    o.z = 1.f / (1.f + __expf(-(t2 * p.z + d2 * q.z + dg * r.z + b.z)));
    o.w = 1.f / (1.f + __expf(-(t2 * p.w + d2 * q.w + dg * r.w + b.w)));
    *(float4*)(out + i * 512 + c4) = o;
}

// ---------------- launch ----------------
extern "C" void kernel_launch(void* const* d_in, const int* in_sizes, int n_in,
                              void* d_out, int out_size) {
    const float* x = 0;  const void* ei = 0;  const float* ew = 0;
    const float* u128 = 0; const float* v128 = 0;
    const float* W2 = 0; const float* b2 = 0;
    const float* W3 = 0; const float* b3 = 0;
    int ei_words = 0;
    for (int i = 0; i < n_in; i++) {
        int sz = in_sizes[i];
        const void* p = d_in[i];
        switch (sz) {
            case 10000:  x  = (const float*)p; break;
            case 320000: ei = p; ei_words = sz; break;
            case 640000: ei = p; ei_words = sz; break;
            case 160000: ew = (const float*)p; break;
            case 128:    if (!u128) u128 = (const float*)p; else v128 = (const float*)p; break;
            case 32768:  W2 = (const float*)p; break;
            case 256:    b2 = (const float*)p; break;
            case 131072: W3 = (const float*)p; break;
            case 512:    b3 = (const float*)p; break;
            default: break;
        }
    }
    if (!x || !ei || !ew || !u128 || !v128 || !W2 || !b2 || !W3 || !b3) {
        x  = (const float*)d_in[0]; ei = d_in[1]; ew = (const float*)d_in[2];
        u128 = (const float*)d_in[3]; v128 = (const float*)d_in[4];
        W2 = (const float*)d_in[5]; b2 = (const float*)d_in[6];
        W3 = (const float*)d_in[7]; b3 = (const float*)d_in[8];
        ei_words = in_sizes[1];
    }
    int force = (ei_words == 4 * NE) ? 0 : -1;
    float* out = (float*)d_out;

    // weight-factor GEMVs (independent of graph)
    gemv2_kernel<<<1, 256>>>(u128, v128, W2);
    gemv3_kernel<<<1, 512>>>(W3, b2);

    // CSR build
    detect_kernel<<<1, 32>>>((const long long*)ei, force);
    zero_cnt_kernel<<<(NN + 255) / 256, 256>>>();
    hist_kernel<<<(NE + 255) / 256, 256>>>(ei);
    scan_kernel<<<1, 1024>>>();
    scatter_kernel<<<(NE + 255) / 256, 256>>>(ei, ew);

    // SpMV chain: (s, deg) -> (t, d2) -> t2
    spmv_pass1_kernel<<<(NN + 255) / 256, 256>>>(x);
    spmv_pass2_kernel<<<(NN + 255) / 256, 256>>>();
    spmv_pass3_kernel<<<(NN + 255) / 256, 256>>>();

    // output
    final_kernel<<<(NN * 128 + 255) / 256, 256>>>(b3, out);
}

// round 11
// speedup vs baseline: 8.6266x; 1.3746x over previous
#include <cuda_runtime.h>
#include <cstdint>

#define NN 10000
#define NE 160000
#define NBLK 625           // NBLK * 256 == NE exactly
#define NTHR 256

// ---------------- device scratch (no allocations allowed) ----------------
// RULE (round-6): never pass __device__ symbols as kernel args from host
// (GB300 ATS resolves the host .bss shadow silently). Device-code refs only.
__device__ int   g_is32;
__device__ volatile unsigned g_bar;
__device__ float g_sx[NN];    // s  = A x
__device__ float g_deg[NN];   // deg = A 1
__device__ float g_t[NN];     // t  = A s
__device__ float g_d2[NN];    // d2 = A deg
__device__ float g_t2[NN];    // t2 = A t
__device__ __align__(16) float g_p[512];   // p = (w1 W2) W3
__device__ __align__(16) float g_q[512];   // q = (b1 W2) W3
__device__ __align__(16) float g_r[512];   // r = b2 W3

// ================= kernel 1: setup (1 block, 512 threads) =================
// - reset grid barrier, detect edge dtype
// - zero the 5 per-node accumulators
// - disambiguate W1/b1 (bias is exactly zero; Glorot weights are not)
// - u = w1 W2, v = b1 W2 (smem), then p = u W3, q = v W3, r = b2 W3
__global__ void setup_kernel(const long long* __restrict__ ei, int force,
                             const float* __restrict__ u128,
                             const float* __restrict__ v128,
                             const float* __restrict__ W2,
                             const float* __restrict__ b2,
                             const float* __restrict__ W3) {
    __shared__ float su[256], sv[256];
    __shared__ int any;
    int t = threadIdx.x;

    if (t == 0) {
        g_bar = 0;
        if (force >= 0) {
            g_is32 = force;
        } else {
            int is32 = 0;
            for (int i = 0; i < 64; i++) {
                long long v = ei[i];
                if (v < 0 || v >= NN) { is32 = 1; break; }
            }
            g_is32 = is32;
        }
        any = 0;
    }
    __syncthreads();

    // zero accumulators (5 * NN floats)
    for (int i = t; i < NN; i += 512) {
        g_sx[i] = 0.f; g_deg[i] = 0.f; g_t[i] = 0.f; g_d2[i] = 0.f; g_t2[i] = 0.f;
    }

    if (t < 128 && u128[t] != 0.0f) atomicExch(&any, 1);
    __syncthreads();
    const float* w1 = (any == 0) ? v128 : u128;
    const float* b1 = (any == 0) ? u128 : v128;

    if (t < 256) {
        float u = 0.f, v = 0.f;
#pragma unroll 8
        for (int j = 0; j < 128; j++) {
            float wv = W2[j * 256 + t];
            u += w1[j] * wv;
            v += b1[j] * wv;
        }
        su[t] = u;
        sv[t] = v;
    }
    __syncthreads();

    {
        float p = 0.f, q = 0.f, r = 0.f;
#pragma unroll 8
        for (int k = 0; k < 256; k++) {
            float wv = W3[k * 512 + t];
            p += su[k] * wv;
            q += sv[k] * wv;
            r += b2[k] * wv;
        }
        g_p[t] = p;
        g_q[t] = q;
        g_r[t] = r;
    }
}

// ================= kernel 2: megakernel (625 blocks x 256) ================
__device__ __forceinline__ void grid_barrier(unsigned target) {
    __syncthreads();
    if (threadIdx.x == 0) {
        __threadfence();
        atomicAdd((unsigned*)&g_bar, 1u);
        while (g_bar < target) { }
        __threadfence();
    }
    __syncthreads();
}

__global__ void __launch_bounds__(NTHR, 5)
mega_kernel(const void* __restrict__ ei,
            const float* __restrict__ ew,
            const float* __restrict__ x,
            const float* __restrict__ b3,
            float* __restrict__ out) {
    int e = blockIdx.x * NTHR + threadIdx.x;   // exactly one thread per edge
    int is32 = g_is32;
    int s, d;
    if (is32) {
        const int* p = (const int*)ei;
        s = p[e];
        d = p[NE + e];
    } else {
        const long long* p = (const long long*)ei;
        s = (int)p[e];
        d = (int)p[NE + e];
    }
    float w = ew[e];
    bool ok = (s >= 0 && s < NN && d >= 0 && d < NN);

    // pass 1: s = A x ; deg = A 1
    if (ok) {
        atomicAdd(&g_sx[d], w * x[s]);
        atomicAdd(&g_deg[d], w);
    }
    grid_barrier(1u * NBLK);

    // pass 2: t = A s ; d2 = A deg
    if (ok) {
        atomicAdd(&g_t[d], w * g_sx[s]);
        atomicAdd(&g_d2[d], w * g_deg[s]);
    }
    grid_barrier(2u * NBLK);

    // pass 3: t2 = A t
    if (ok) {
        atomicAdd(&g_t2[d], w * g_t[s]);
    }
    grid_barrier(3u * NBLK);

    // final: out[i,c] = sigmoid(t2_i p_c + d2_i q_c + deg_i r_c + b3_c)
    __shared__ float sp[512], sq[512], sr[512], sb[512];
    for (int c = threadIdx.x; c < 512; c += NTHR) {
        sp[c] = g_p[c];
        sq[c] = g_q[c];
        sr[c] = g_r[c];
        sb[c] = b3[c];
    }
    __syncthreads();

    // NN*128 float4 work items over NE threads: 8 each
    for (int idx = e; idx < NN * 128; idx += NE) {
        int i = idx >> 7;
        int c4 = (idx & 127) * 4;
        float t2 = g_t2[i], d2 = g_d2[i], dg = g_deg[i];
        float4 p = *(const float4*)(sp + c4);
        float4 q = *(const float4*)(sq + c4);
        float4 r = *(const float4*)(sr + c4);
        float4 b = *(const float4*)(sb + c4);
        float4 o;
        o.x = 1.f / (1.f + __expf(-(t2 * p.x + d2 * q.x + dg * r.x + b.x)));
        o.y = 1.f / (1.f + __expf(-(t2 * p.y + d2 * q.y + dg * r.y + b.y)));
        o.z = 1.f / (1.f + __expf(-(t2 * p.z + d2 * q.z + dg * r.z + b.z)));
        o.w = 1.f / (1.f + __expf(-(t2 * p.w + d2 * q.w + dg * r.w + b.w)));
        *(float4*)(out + i * 512 + c4) = o;
    }
}

// ---------------- launch ----------------
extern "C" void kernel_launch(void* const* d_in, const int* in_sizes, int n_in,
                              void* d_out, int out_size) {
    const float* x = 0;  const void* ei = 0;  const float* ew = 0;
    const float* u128 = 0; const float* v128 = 0;
    const float* W2 = 0; const float* b2 = 0;
    const float* W3 = 0; const float* b3 = 0;
    int ei_words = 0;
    for (int i = 0; i < n_in; i++) {
        int sz = in_sizes[i];
        const void* p = d_in[i];
        switch (sz) {
            case 10000:  x  = (const float*)p; break;
            case 320000: ei = p; ei_words = sz; break;
            case 640000: ei = p; ei_words = sz; break;
            case 160000: ew = (const float*)p; break;
            case 128:    if (!u128) u128 = (const float*)p; else v128 = (const float*)p; break;
            case 32768:  W2 = (const float*)p; break;
            case 256:    b2 = (const float*)p; break;
            case 131072: W3 = (const float*)p; break;
            case 512:    b3 = (const float*)p; break;
            default: break;
        }
    }
    if (!x || !ei || !ew || !u128 || !v128 || !W2 || !b2 || !W3 || !b3) {
        x  = (const float*)d_in[0]; ei = d_in[1]; ew = (const float*)d_in[2];
        u128 = (const float*)d_in[3]; v128 = (const float*)d_in[4];
        W2 = (const float*)d_in[5]; b2 = (const float*)d_in[6];
        W3 = (const float*)d_in[7]; b3 = (const float*)d_in[8];
        ei_words = in_sizes[1];
    }
    int force = (ei_words == 4 * NE) ? 0 : -1;
    float* out = (float*)d_out;

    setup_kernel<<<1, 512>>>((const long long*)ei, force, u128, v128, W2, b2, W3);
    mega_kernel<<<NBLK, NTHR>>>(ei, ew, x, b3, out);
}